// round 17
// baseline (speedup 1.0000x reference)
#include <cuda_runtime.h>
#include <cuda_fp16.h>
#include <cstdint>

// Problem constants
#define Bn 256
#define Nn 1152        // 32*6*6 input capsules
#define On 10
#define En 16
#define OE 160         // On*En
#define Dn 8
#define NCH 32         // n per block
#define TILES (Nn / NCH)  // 36
#define BCH 8          // b per block
#define USTR 84        // u_s b-row stride in half2 units (80 + 4 pad)

// Scratch (device globals) — NO u_hat materialization.
__device__ float g_part[TILES * Bn * OE];   // per-tile partials (5.9 MB)
__device__ float g_v[Bn * OE];              // v0, then v0+v1 (the logit vector)

// ---------------------------------------------------------------------------
// squash over E=16 within a warp-half. Requires fully-active warps.
__device__ __forceinline__ float squash_val(float sv) {
    float sq = sv * sv;
    sq += __shfl_xor_sync(0xffffffffu, sq, 1);
    sq += __shfl_xor_sync(0xffffffffu, sq, 2);
    sq += __shfl_xor_sync(0xffffffffu, sq, 4);
    sq += __shfl_xor_sync(0xffffffffu, sq, 8);
    return sv * sq / (1.0f + sq) / (sqrtf(sq) + 1e-6f);
}

// ---------------------------------------------------------------------------
// x tile loader: xs[b][n][d] for (b0..b0+7, n0..n0+31). 512 float4.
__device__ __forceinline__ void load_x_tile(float (*xs)[NCH][Dn],
                                            const float* __restrict__ x,
                                            int b0, int n0, int t) {
    for (int i = t; i < BCH * NCH * Dn / 4; i += 320) {  // 512
        int b = i >> 6, q = i & 63;                      // 64 float4 per b
        float4 v = *(const float4*)(x + ((size_t)(b0 + b) * Nn + n0) * Dn + q * 4);
        int n = q >> 1, h = q & 1;
        *(float4*)(&xs[b][n][h * 4]) = v;
    }
}

// ---------------------------------------------------------------------------
// K_S0: recompute u on the fly, accumulate s0 partials. No u store anywhere.
// grid (36 n-tiles, 32 b-blocks), 320 thr = 4 n-subranges (g) x 80 (o,e2).
__global__ __launch_bounds__(320) void k_s0(const float* __restrict__ x,
                                            const float* __restrict__ W) {
    int tile = blockIdx.x, n0 = tile * NCH;
    int b0 = blockIdx.y * BCH;
    int t = threadIdx.x;

    __shared__ float  xs[BCH][NCH][Dn];   // 8 KB
    __shared__ float2 sp[4][BCH][80];     // 20 KB
    load_x_tile(xs, x, b0, n0, t);
    __syncthreads();

    int g = t / 80, p = t - g * 80;       // g: n-subrange of 8
    int o = p >> 3, e2 = p & 7;

    float2 acc[BCH];
#pragma unroll
    for (int b = 0; b < BCH; b++) acc[b] = make_float2(0.f, 0.f);

#pragma unroll 2
    for (int i = 0; i < 8; i++) {
        int n = g * 8 + i;
        float2 w[8];
        const float2* wp = (const float2*)(W + (size_t)((n0 + n) * On + o) * (Dn * En)) + e2;
#pragma unroll
        for (int d = 0; d < 8; d++) w[d] = wp[d * 8];
#pragma unroll
        for (int b = 0; b < BCH; b++) {
            float4 xa = *(const float4*)&xs[b][n][0];
            float4 xb = *(const float4*)&xs[b][n][4];
            float u0, u1;
            u0 = w[0].x * xa.x; u1 = w[0].y * xa.x;
            u0 = fmaf(w[1].x, xa.y, u0); u1 = fmaf(w[1].y, xa.y, u1);
            u0 = fmaf(w[2].x, xa.z, u0); u1 = fmaf(w[2].y, xa.z, u1);
            u0 = fmaf(w[3].x, xa.w, u0); u1 = fmaf(w[3].y, xa.w, u1);
            u0 = fmaf(w[4].x, xb.x, u0); u1 = fmaf(w[4].y, xb.x, u1);
            u0 = fmaf(w[5].x, xb.y, u0); u1 = fmaf(w[5].y, xb.y, u1);
            u0 = fmaf(w[6].x, xb.z, u0); u1 = fmaf(w[6].y, xb.z, u1);
            u0 = fmaf(w[7].x, xb.w, u0); u1 = fmaf(w[7].y, xb.w, u1);
            acc[b].x += u0; acc[b].y += u1;
        }
    }
#pragma unroll
    for (int b = 0; b < BCH; b++) sp[g][b][p] = acc[b];
    __syncthreads();

    for (int i = t; i < BCH * 80; i += 320) {
        int b = i / 80, pp = i - b * 80;
        float2 r = sp[0][b][pp];
        float2 r1 = sp[1][b][pp], r2 = sp[2][b][pp], r3 = sp[3][b][pp];
        r.x += r1.x + r2.x + r3.x;
        r.y += r1.y + r2.y + r3.y;
        *(float2*)(g_part + ((size_t)tile * Bn + b0 + b) * OE + 2 * pp) = r;
    }
}

// ---------------------------------------------------------------------------
// K_ITER: one routing iteration, u recomputed into an smem fp16 tile.
//   Phase 1: u[b][n][oe] -> u_s (fp16, same rounding as old stored u_hat)
//   Phase 2: logits = u . g_v    Phase 3: softmax_o (in place)
//   Phase 4: partial s[b][oe] = sum_n c*u  -> g_part (each (b,oe) one thread)
// grid (36, 32), 320 threads, 65 KB dynamic smem -> 3 CTAs/SM.
__global__ __launch_bounds__(320, 3) void k_iter(const float* __restrict__ x,
                                                 const float* __restrict__ W) {
    extern __shared__ char smraw[];
    float (*xs)[NCH][Dn] = (float (*)[NCH][Dn])smraw;          // 8192 B
    float* v_s = (float*)(smraw + 8192);                       // 5120 B [b][oe]
    __half2* u_s = (__half2*)(smraw + 8192 + 5120);            // 43008 B [n][b][USTR]
    float* b1s = (float*)(smraw + 8192 + 5120 + NCH * BCH * USTR * 4);  // 10240 B [b][n][o]

    int tile = blockIdx.x, n0 = tile * NCH;
    int b0 = blockIdx.y * BCH;
    int t = threadIdx.x;

    load_x_tile(xs, x, b0, n0, t);
    for (int i = t; i < BCH * OE; i += 320) v_s[i] = g_v[b0 * OE + i];
    __syncthreads();

    // Phase 1: recompute u -> u_s
    {
        int g = t / 80, p = t - g * 80;
        int o = p >> 3, e2 = p & 7;
#pragma unroll 2
        for (int i = 0; i < 8; i++) {
            int n = g * 8 + i;
            float2 w[8];
            const float2* wp = (const float2*)(W + (size_t)((n0 + n) * On + o) * (Dn * En)) + e2;
#pragma unroll
            for (int d = 0; d < 8; d++) w[d] = wp[d * 8];
#pragma unroll
            for (int b = 0; b < BCH; b++) {
                float4 xa = *(const float4*)&xs[b][n][0];
                float4 xb = *(const float4*)&xs[b][n][4];
                float u0, u1;
                u0 = w[0].x * xa.x; u1 = w[0].y * xa.x;
                u0 = fmaf(w[1].x, xa.y, u0); u1 = fmaf(w[1].y, xa.y, u1);
                u0 = fmaf(w[2].x, xa.z, u0); u1 = fmaf(w[2].y, xa.z, u1);
                u0 = fmaf(w[3].x, xa.w, u0); u1 = fmaf(w[3].y, xa.w, u1);
                u0 = fmaf(w[4].x, xb.x, u0); u1 = fmaf(w[4].y, xb.x, u1);
                u0 = fmaf(w[5].x, xb.y, u0); u1 = fmaf(w[5].y, xb.y, u1);
                u0 = fmaf(w[6].x, xb.z, u0); u1 = fmaf(w[6].y, xb.z, u1);
                u0 = fmaf(w[7].x, xb.w, u0); u1 = fmaf(w[7].y, xb.w, u1);
                u_s[(n * BCH + b) * USTR + p] = __floats2half2_rn(u0, u1);
            }
        }
    }
    __syncthreads();

    // Phase 2: logits. t -> (n = t/10, o = t%10); loop b = 0..7.
    {
        int n = t / 10, oo = t - n * 10;
#pragma unroll
        for (int b = 0; b < BCH; b++) {
            const uint4* ur = (const uint4*)(u_s + (n * BCH + b) * USTR + oo * 8);
            const float4* vf = (const float4*)(v_s + b * OE + oo * En);
            uint4 ua = ur[0], ub = ur[1];
            float4 v0 = vf[0], v1 = vf[1], v2 = vf[2], v3 = vf[3];
            float2 f;
            float bb = 0.f;
            f = __half22float2(*(__half2*)&ua.x); bb = fmaf(f.x, v0.x, fmaf(f.y, v0.y, bb));
            f = __half22float2(*(__half2*)&ua.y); bb = fmaf(f.x, v0.z, fmaf(f.y, v0.w, bb));
            f = __half22float2(*(__half2*)&ua.z); bb = fmaf(f.x, v1.x, fmaf(f.y, v1.y, bb));
            f = __half22float2(*(__half2*)&ua.w); bb = fmaf(f.x, v1.z, fmaf(f.y, v1.w, bb));
            f = __half22float2(*(__half2*)&ub.x); bb = fmaf(f.x, v2.x, fmaf(f.y, v2.y, bb));
            f = __half22float2(*(__half2*)&ub.y); bb = fmaf(f.x, v2.z, fmaf(f.y, v2.w, bb));
            f = __half22float2(*(__half2*)&ub.z); bb = fmaf(f.x, v3.x, fmaf(f.y, v3.y, bb));
            f = __half22float2(*(__half2*)&ub.w); bb = fmaf(f.x, v3.z, fmaf(f.y, v3.w, bb));
            b1s[b * 320 + t] = bb;   // (b*32+n)*10+oo
        }
    }
    __syncthreads();

    // Phase 3: softmax over o in place, one thread per (b,n)
    if (t < BCH * NCH) {
        float* br = b1s + (t >> 5) * 320 + (t & 31) * On;
        float m = br[0];
#pragma unroll
        for (int oo = 1; oo < On; oo++) m = fmaxf(m, br[oo]);
        float ex[On]; float ssum = 0.f;
#pragma unroll
        for (int oo = 0; oo < On; oo++) { ex[oo] = __expf(br[oo] - m); ssum += ex[oo]; }
        float inv = 1.0f / ssum;
#pragma unroll
        for (int oo = 0; oo < On; oo++) br[oo] = ex[oo] * inv;
    }
    __syncthreads();

    // Phase 4: weighted sums. t -> (b = t/40, oq = (t%40)/4, j = t%4).
    {
        int b = t / 40, pq = t - b * 40, oq = pq >> 2, j = pq & 3;
        float4 a = make_float4(0.f, 0.f, 0.f, 0.f);
        const float* cb = b1s + b * 320 + oq;
        const __half2* ub = u_s + b * USTR + oq * 8 + 2 * j;
#pragma unroll 8
        for (int n = 0; n < NCH; n++) {
            float c = cb[n * On];
            uint2 uu = *(const uint2*)(ub + n * (BCH * USTR));
            float2 f0 = __half22float2(*(__half2*)&uu.x);
            float2 f1 = __half22float2(*(__half2*)&uu.y);
            a.x = fmaf(c, f0.x, a.x);
            a.y = fmaf(c, f0.y, a.y);
            a.z = fmaf(c, f1.x, a.z);
            a.w = fmaf(c, f1.y, a.w);
        }
        *(float4*)(g_part + ((size_t)tile * Bn + b0 + b) * OE + oq * En + 4 * j) = a;
    }
}

// ---------------------------------------------------------------------------
// Reduce 36 tile partials -> s -> squash. 640 thr = 4 groups x 160.
// MODE 0: v0 = squash(0.1*s) -> g_v ; MODE 1: g_v += squash(s) ; MODE 2: out.
template <int MODE>
__global__ void k_finish(float* __restrict__ out) {
    constexpr int G = 4, PER = TILES / G;  // 9
    __shared__ float red[G][OE];

    int b = blockIdx.x, t = threadIdx.x;   // 640
    int g = t / OE, oe = t - g * OE;
    float acc = 0.f;
#pragma unroll
    for (int i = 0; i < PER; i++)
        acc += g_part[((size_t)(g * PER + i) * Bn + b) * OE + oe];
    red[g][oe] = acc;
    __syncthreads();

    if (t < OE) {
        float s = ((red[0][t] + red[1][t]) + red[2][t]) + red[3][t];
        if (MODE == 0)      g_v[b * OE + t]  = squash_val(s * 0.1f);
        else if (MODE == 1) g_v[b * OE + t] += squash_val(s);
        else                out[b * OE + t]  = squash_val(s);
    }
}

// ---------------------------------------------------------------------------
extern "C" void kernel_launch(void* const* d_in, const int* in_sizes, int n_in,
                              void* d_out, int out_size) {
    const float* x = (const float*)d_in[0];
    const float* W = (const float*)d_in[1];
    if (n_in >= 2 && in_sizes[0] == 1474560) {  // defensive: swapped order
        x = (const float*)d_in[1];
        W = (const float*)d_in[0];
    }
    float* out = (float*)d_out;

    const int smem_iter = 8192 + 5120 + NCH * BCH * USTR * 4 + BCH * NCH * On * 4;  // 66560
    cudaFuncSetAttribute(k_iter, cudaFuncAttributeMaxDynamicSharedMemorySize, smem_iter);

    dim3 grid(TILES, Bn / BCH);                    // (36, 32)
    k_s0<<<grid, 320>>>(x, W);                     // s0 partials (recompute, no store)
    k_finish<0><<<Bn, 4 * OE>>>(nullptr);          // v0
    k_iter<<<grid, 320, smem_iter>>>(x, W);        // iter 1 partials (recompute)
    k_finish<1><<<Bn, 4 * OE>>>(nullptr);          // v1, g_v = v0+v1
    k_iter<<<grid, 320, smem_iter>>>(x, W);        // iter 2 partials (recompute)
    k_finish<2><<<Bn, 4 * OE>>>(out);              // v2 -> d_out
}